// round 12
// baseline (speedup 1.0000x reference)
#include <cuda_runtime.h>
#include <cuda_bf16.h>
#include <cuda_fp16.h>
#include <cstdint>

#define N_NODES 100000
#define N_EDGES 1600000
#define D 128
#define CAP 64
#define OVF_CAP 8192

// ---------------- scratch (static device globals; no runtime allocation) ----
__device__ __half g_suph[(size_t)N_NODES * D];         // x @ W in fp16 (25.6 MB)
__device__ int    g_deg[N_NODES];
__device__ int2   g_bpack[(size_t)N_NODES * CAP];      // (src, val bits) packed
__device__ int    g_ovfn;
__device__ int    g_ovf_src[OVF_CAP];
__device__ int    g_ovf_dst[OVF_CAP];
__device__ float  g_ovf_val[OVF_CAP];

__device__ __forceinline__ uint32_t cvt_tf32(float f) {
    uint32_t r;
    asm("cvt.rna.tf32.f32 %0, %1;" : "=r"(r) : "f"(f));
    return r;
}
__device__ __forceinline__ uint32_t smem_u32(const void* p) {
    uint32_t a;
    asm("{ .reg .u64 t; cvta.to.shared.u64 t, %1; cvt.u32.u64 %0, t; }"
        : "=r"(a) : "l"(p));
    return a;
}
#define CP_ASYNC16(saddr, gptr) \
    asm volatile("cp.async.cg.shared.global [%0], [%1], 16;" :: "r"(saddr), "l"(gptr))
#define CP_COMMIT()  asm volatile("cp.async.commit_group;")
#define CP_WAIT0()   asm volatile("cp.async.wait_group 0;")
// named barrier for the 8 GEMM warps only (bucket warps never join it)
#define GEMM_BAR()   asm volatile("bar.sync 1, 256;" ::: "memory")

// mma.sync m16n8k8 tf32: D += A*B (A row-major 16x8, B col-major 8x8)
#define MMA_TF32(d0, d1, d2, d3, a0, a1, a2, a3, b0, b1)                        \
    asm volatile(                                                               \
        "mma.sync.aligned.m16n8k8.row.col.f32.tf32.tf32.f32 "                   \
        "{%0,%1,%2,%3}, {%4,%5,%6,%7}, {%8,%9}, {%0,%1,%2,%3};"                 \
        : "+f"(d0), "+f"(d1), "+f"(d2), "+f"(d3)                                \
        : "r"(a0), "r"(a1), "r"(a2), "r"(a3), "r"(b0), "r"(b1))

// ---------------- 1) zero counters ------------------------------------------
__global__ void zero_kernel() {
    int i = blockIdx.x * blockDim.x + threadIdx.x;
    if (i < N_NODES) g_deg[i] = 0;
    if (i == 0) g_ovfn = 0;
}

// ---------------- 2+3) fused: GEMM (warps 0-7) + edge bucketing (warps 8-11)-
// Persistent 148 CTAs x 384 threads. GEMM warps: tile loop with cp.async
// double-buffered A, B tf32 in smem, named barrier (id 1, 256 threads).
// Bucket warps: grid-stride the edge list, scatter (src,val) into per-dst
// buckets. Independent work, different pipes -> overlaps with MMA.
#define A_STRIDE 132
#define B_STRIDE 136
#define M_TILE 128
#define BUF_U32 (M_TILE * A_STRIDE)                   // 16896 u32 = 67584 B
#define B_OFF   (2 * BUF_U32)                         // after both A buffers
#define SM_GEMM (2 * BUF_U32 * 4 + 128 * B_STRIDE * 4)  // 204800 B
#define TILES ((N_NODES + M_TILE - 1) / M_TILE)       // 782
#define GEMM_CTAS 148
#define BUCKET_THREADS (GEMM_CTAS * 128)              // 18944

__device__ __forceinline__ void stage_async(uint32_t sbuf,
                                            const float* __restrict__ x,
                                            int tile, int tid) {
    int row0 = tile * M_TILE;
    #pragma unroll
    for (int i = 0; i < 16; i++) {
        int idx = tid + i * 256;
        int r = idx >> 5, c4 = idx & 31;
        int gr = row0 + r;
        if (gr >= N_NODES) gr = N_NODES - 1;
        uint32_t sa = sbuf + (uint32_t)(r * A_STRIDE + c4 * 4) * 4u;
        CP_ASYNC16(sa, x + (size_t)gr * 128 + c4 * 4);
    }
}

__global__ __launch_bounds__(384, 1)
void gemm_bucket_kernel(const float* __restrict__ x,
                        const float* __restrict__ w,
                        __half* __restrict__ suph,
                        const int* __restrict__ esrc,
                        const int* __restrict__ edst,
                        const float* __restrict__ aval) {
    extern __shared__ uint32_t sm[];
    int tid  = threadIdx.x;
    int wid  = tid >> 5;

    // ---------------- bucket role: warps 8-11 -------------------------------
    if (wid >= 8) {
        int e = blockIdx.x * 128 + (tid - 256);
        for (; e < N_EDGES; e += BUCKET_THREADS) {
            int d = edst[e];
            int s = esrc[e];
            float v = aval[e];
            int p = atomicAdd(&g_deg[d], 1);
            if (p < CAP) {
                g_bpack[d * CAP + p] = make_int2(s, __float_as_int(v));
            } else {
                int o = atomicAdd(&g_ovfn, 1);
                if (o < OVF_CAP) {
                    g_ovf_src[o] = s;
                    g_ovf_dst[o] = d;
                    g_ovf_val[o] = v;
                }
            }
        }
        return;
    }

    // ---------------- GEMM role: warps 0-7 ----------------------------------
    uint32_t* bufA[2] = { sm, sm + BUF_U32 };
    uint32_t* Bs = sm + B_OFF;               // [128][B_STRIDE] tf32
    uint32_t sbase = smem_u32(sm);

    int lane = tid & 31;
    int wr   = wid >> 2;        // warp row 0..1 -> rows wr*64
    int wc   = wid & 3;         // warp col 0..3 -> cols wc*32
    int lr   = lane >> 2;       // 0..7
    int lc   = lane & 3;        // 0..3

    int tile = blockIdx.x;
    if (tile >= TILES) return;

    // stage first A tile async, convert B to smem meanwhile
    int cur = 0;
    stage_async(sbase, x, tile, tid);
    CP_COMMIT();
    for (int idx = tid; idx < 128 * 32; idx += 256) {
        int k = idx >> 5, c4 = idx & 31;
        float4 v = ((const float4*)w)[k * 32 + c4];
        uint4 t;
        t.x = cvt_tf32(v.x); t.y = cvt_tf32(v.y);
        t.z = cvt_tf32(v.z); t.w = cvt_tf32(v.w);
        *(uint4*)&Bs[k * B_STRIDE + c4 * 4] = t;
    }
    CP_WAIT0();
    GEMM_BAR();

    while (tile < TILES) {
        int next = tile + GEMM_CTAS;
        if (next < TILES) {
            stage_async(sbase + (cur ^ 1) * (BUF_U32 * 4), x, next, tid);
            CP_COMMIT();
        }

        const uint32_t* As = bufA[cur];
        float acc[4][4][4];
        #pragma unroll
        for (int m = 0; m < 4; m++)
            #pragma unroll
            for (int n = 0; n < 4; n++)
                #pragma unroll
                for (int q = 0; q < 4; q++) acc[m][n][q] = 0.f;

        #pragma unroll 4
        for (int ks = 0; ks < 16; ks++) {
            int k0 = ks * 8;
            uint32_t af[4][4], bf[4][2];
            #pragma unroll
            for (int n = 0; n < 4; n++) {
                int nn = wc * 32 + n * 8 + lr;
                bf[n][0] = Bs[(k0 + lc) * B_STRIDE + nn];
                bf[n][1] = Bs[(k0 + lc + 4) * B_STRIDE + nn];
            }
            #pragma unroll
            for (int m = 0; m < 4; m++) {
                int r = wr * 64 + m * 16 + lr;
                af[m][0] = As[r * A_STRIDE + k0 + lc];
                af[m][1] = As[(r + 8) * A_STRIDE + k0 + lc];
                af[m][2] = As[r * A_STRIDE + k0 + lc + 4];
                af[m][3] = As[(r + 8) * A_STRIDE + k0 + lc + 4];
            }
            #pragma unroll
            for (int m = 0; m < 4; m++)
                #pragma unroll
                for (int n = 0; n < 4; n++)
                    MMA_TF32(acc[m][n][0], acc[m][n][1], acc[m][n][2], acc[m][n][3],
                             af[m][0], af[m][1], af[m][2], af[m][3],
                             bf[n][0], bf[n][1]);
        }

        // epilogue: fp16 (RN). c0,c1 at (row, 2*lc), c2,c3 at (row+8, 2*lc)
        int row0 = tile * M_TILE;
        #pragma unroll
        for (int m = 0; m < 4; m++) {
            int r = row0 + wr * 64 + m * 16 + lr;
            #pragma unroll
            for (int n = 0; n < 4; n++) {
                int col = wc * 32 + n * 8 + lc * 2;
                if (r < N_NODES)
                    *(__half2*)(suph + (size_t)r * 128 + col) =
                        __floats2half2_rn(acc[m][n][0], acc[m][n][1]);
                if (r + 8 < N_NODES)
                    *(__half2*)(suph + (size_t)(r + 8) * 128 + col) =
                        __floats2half2_rn(acc[m][n][2], acc[m][n][3]);
            }
        }

        if (next < TILES) CP_WAIT0();
        GEMM_BAR();
        cur ^= 1;
        tile = next;
    }
}

// ---------------- 4) gather + bias + residual + relu ------------------------
// 16 lanes per node (2 nodes/warp). Lane sl owns 8 halfs (one 16B load per
// edge). Two independent edge streams per warp -> 2x MLP vs warp-per-node.
__global__ __launch_bounds__(256)
void gather_kernel(const float* __restrict__ y,
                   const float* __restrict__ bias,
                   float* __restrict__ out) {
    int gt   = blockIdx.x * 256 + threadIdx.x;
    int node = gt >> 4;
    int sl   = threadIdx.x & 15;
    if (node >= N_NODES) return;

    const uint4* sup4 = (const uint4*)g_suph;    // 8 halfs per uint4; row=16
    float4 b0 = ((const float4*)bias)[sl * 2];
    float4 b1 = ((const float4*)bias)[sl * 2 + 1];
    float4 a0 = ((const float4*)y)[(size_t)node * 32 + sl * 2];
    float4 a1 = ((const float4*)y)[(size_t)node * 32 + sl * 2 + 1];
    a0.x += b0.x; a0.y += b0.y; a0.z += b0.z; a0.w += b0.w;
    a1.x += b1.x; a1.y += b1.y; a1.z += b1.z; a1.w += b1.w;

    int dn = g_deg[node];
    int m  = dn < CAP ? dn : CAP;
    int base = node * CAP;

    #pragma unroll 2
    for (int j = 0; j < m; j++) {
        int2 e = g_bpack[base + j];
        float v = __int_as_float(e.y);
        uint4 p = sup4[(size_t)e.x * 16 + sl];
        float2 f0 = __half22float2(*(__half2*)&p.x);
        float2 f1 = __half22float2(*(__half2*)&p.y);
        float2 f2 = __half22float2(*(__half2*)&p.z);
        float2 f3 = __half22float2(*(__half2*)&p.w);
        a0.x = fmaf(v, f0.x, a0.x); a0.y = fmaf(v, f0.y, a0.y);
        a0.z = fmaf(v, f1.x, a0.z); a0.w = fmaf(v, f1.y, a0.w);
        a1.x = fmaf(v, f2.x, a1.x); a1.y = fmaf(v, f2.y, a1.y);
        a1.z = fmaf(v, f3.x, a1.z); a1.w = fmaf(v, f3.y, a1.w);
    }

    if (dn > CAP) {  // statistically never; correctness safety net
        int oc = g_ovfn;
        if (oc > OVF_CAP) oc = OVF_CAP;
        for (int k = 0; k < oc; k++) {
            if (g_ovf_dst[k] == node) {
                float v = g_ovf_val[k];
                uint4 p = sup4[(size_t)g_ovf_src[k] * 16 + sl];
                float2 f0 = __half22float2(*(__half2*)&p.x);
                float2 f1 = __half22float2(*(__half2*)&p.y);
                float2 f2 = __half22float2(*(__half2*)&p.z);
                float2 f3 = __half22float2(*(__half2*)&p.w);
                a0.x = fmaf(v, f0.x, a0.x); a0.y = fmaf(v, f0.y, a0.y);
                a0.z = fmaf(v, f1.x, a0.z); a0.w = fmaf(v, f1.y, a0.w);
                a1.x = fmaf(v, f2.x, a1.x); a1.y = fmaf(v, f2.y, a1.y);
                a1.z = fmaf(v, f3.x, a1.z); a1.w = fmaf(v, f3.y, a1.w);
            }
        }
    }

    a0.x = fmaxf(a0.x, 0.f); a0.y = fmaxf(a0.y, 0.f);
    a0.z = fmaxf(a0.z, 0.f); a0.w = fmaxf(a0.w, 0.f);
    a1.x = fmaxf(a1.x, 0.f); a1.y = fmaxf(a1.y, 0.f);
    a1.z = fmaxf(a1.z, 0.f); a1.w = fmaxf(a1.w, 0.f);
    ((float4*)out)[(size_t)node * 32 + sl * 2]     = a0;
    ((float4*)out)[(size_t)node * 32 + sl * 2 + 1] = a1;
}

// ---------------- launch -----------------------------------------------------
extern "C" void kernel_launch(void* const* d_in, const int* in_sizes, int n_in,
                              void* d_out, int out_size) {
    const float* x    = (const float*)d_in[0];
    const float* y    = (const float*)d_in[1];
    const int*   esrc = (const int*)d_in[2];
    const int*   edst = (const int*)d_in[3];
    const float* aval = (const float*)d_in[4];
    const float* w    = (const float*)d_in[5];
    const float* bias = (const float*)d_in[6];
    float* out = (float*)d_out;

    __half* suph;
    cudaGetSymbolAddress((void**)&suph, g_suph);

    cudaFuncSetAttribute(gemm_bucket_kernel,
                         cudaFuncAttributeMaxDynamicSharedMemorySize, SM_GEMM);

    zero_kernel<<<(N_NODES + 255) / 256, 256>>>();
    gemm_bucket_kernel<<<GEMM_CTAS, 384, SM_GEMM>>>(x, w, suph, esrc, edst, aval);
    gather_kernel<<<(N_NODES * 16 + 255) / 256, 256>>>(y, bias, out);
}

// round 15
// speedup vs baseline: 1.0883x; 1.0883x over previous
#include <cuda_runtime.h>
#include <cuda_bf16.h>
#include <cuda_fp16.h>
#include <cstdint>

#define N_NODES 100000
#define N_EDGES 1600000
#define D 128
#define CAP 64
#define OVF_CAP 8192

// ---------------- scratch (static device globals; zero-initialized) ---------
// Self-cleaning protocol: gather_kernel (last consumer) resets g_deg/g_ovfn,
// so every kernel_launch / graph replay starts from zeroed state.
__device__ __half g_suph[(size_t)N_NODES * D];         // x @ W in fp16 (25.6 MB)
__device__ int    g_deg[N_NODES];
__device__ int2   g_bpack[(size_t)N_NODES * CAP];      // (src, val bits) packed
__device__ int    g_ovfn;
__device__ int    g_ovf_src[OVF_CAP];
__device__ int    g_ovf_dst[OVF_CAP];
__device__ float  g_ovf_val[OVF_CAP];

__device__ __forceinline__ uint32_t cvt_tf32(float f) {
    uint32_t r;
    asm("cvt.rna.tf32.f32 %0, %1;" : "=r"(r) : "f"(f));
    return r;
}
__device__ __forceinline__ uint32_t smem_u32(const void* p) {
    uint32_t a;
    asm("{ .reg .u64 t; cvta.to.shared.u64 t, %1; cvt.u32.u64 %0, t; }"
        : "=r"(a) : "l"(p));
    return a;
}
#define CP_ASYNC16(saddr, gptr) \
    asm volatile("cp.async.cg.shared.global [%0], [%1], 16;" :: "r"(saddr), "l"(gptr))
#define CP_COMMIT()  asm volatile("cp.async.commit_group;")
#define CP_WAIT0()   asm volatile("cp.async.wait_group 0;")

// mma.sync m16n8k8 tf32: D += A*B (A row-major 16x8, B col-major 8x8)
#define MMA_TF32(d0, d1, d2, d3, a0, a1, a2, a3, b0, b1)                        \
    asm volatile(                                                               \
        "mma.sync.aligned.m16n8k8.row.col.f32.tf32.tf32.f32 "                   \
        "{%0,%1,%2,%3}, {%4,%5,%6,%7}, {%8,%9}, {%0,%1,%2,%3};"                 \
        : "+f"(d0), "+f"(d1), "+f"(d2), "+f"(d3)                                \
        : "r"(a0), "r"(a1), "r"(a2), "r"(a3), "r"(b0), "r"(b1))

// ---------------- 1) bucket edges by destination (packed 8B stores) ---------
__global__ void bucket_kernel(const int* __restrict__ esrc,
                              const int* __restrict__ edst,
                              const float* __restrict__ aval) {
    int e = blockIdx.x * blockDim.x + threadIdx.x;
    if (e >= N_EDGES) return;
    int d = edst[e];
    int s = esrc[e];
    float v = aval[e];
    int p = atomicAdd(&g_deg[d], 1);
    if (p < CAP) {
        g_bpack[d * CAP + p] = make_int2(s, __float_as_int(v));
    } else {
        int o = atomicAdd(&g_ovfn, 1);
        if (o < OVF_CAP) {
            g_ovf_src[o] = s;
            g_ovf_dst[o] = d;
            g_ovf_val[o] = v;
        }
    }
}

// ---------------- 2) support = x @ W  via mma.sync tf32, fp16 output --------
// Persistent 148 CTAs x 256 threads (8 warps, 2x4). Tile = 128 rows.
// A double-buffered via cp.async, fed RAW fp32 to the tf32 MMA (HW truncates).
// B = W converted to tf32 (RNA) into smem ONCE per CTA; inner loop = LDS+MMA.
#define A_STRIDE 132
#define B_STRIDE 136
#define M_TILE 128
#define BUF_U32 (M_TILE * A_STRIDE)                   // 16896 u32 = 67584 B
#define B_OFF   (2 * BUF_U32)                         // after both A buffers
#define SM_GEMM (2 * BUF_U32 * 4 + 128 * B_STRIDE * 4)  // 204800 B
#define TILES ((N_NODES + M_TILE - 1) / M_TILE)       // 782
#define GEMM_CTAS 148

__device__ __forceinline__ void stage_async(uint32_t sbuf,
                                            const float* __restrict__ x,
                                            int tile, int tid) {
    int row0 = tile * M_TILE;
    #pragma unroll
    for (int i = 0; i < 16; i++) {
        int idx = tid + i * 256;
        int r = idx >> 5, c4 = idx & 31;
        int gr = row0 + r;
        if (gr >= N_NODES) gr = N_NODES - 1;
        uint32_t sa = sbuf + (uint32_t)(r * A_STRIDE + c4 * 4) * 4u;
        CP_ASYNC16(sa, x + (size_t)gr * 128 + c4 * 4);
    }
}

__global__ __launch_bounds__(256, 1)
void gemm_mma_kernel(const float* __restrict__ x,
                     const float* __restrict__ w,
                     __half* __restrict__ suph) {
    extern __shared__ uint32_t sm[];
    uint32_t* bufA[2] = { sm, sm + BUF_U32 };
    uint32_t* Bs = sm + B_OFF;               // [128][B_STRIDE] tf32
    uint32_t sbase = smem_u32(sm);

    int tid  = threadIdx.x;
    int wid  = tid >> 5;
    int lane = tid & 31;
    int wr   = wid >> 2;        // warp row 0..1 -> rows wr*64
    int wc   = wid & 3;         // warp col 0..3 -> cols wc*32
    int lr   = lane >> 2;       // 0..7
    int lc   = lane & 3;        // 0..3

    int tile = blockIdx.x;
    if (tile >= TILES) return;

    // stage first A tile async, convert B to smem meanwhile
    int cur = 0;
    stage_async(sbase, x, tile, tid);
    CP_COMMIT();
    for (int idx = tid; idx < 128 * 32; idx += 256) {
        int k = idx >> 5, c4 = idx & 31;
        float4 v = ((const float4*)w)[k * 32 + c4];
        uint4 t;
        t.x = cvt_tf32(v.x); t.y = cvt_tf32(v.y);
        t.z = cvt_tf32(v.z); t.w = cvt_tf32(v.w);
        *(uint4*)&Bs[k * B_STRIDE + c4 * 4] = t;
    }
    CP_WAIT0();
    __syncthreads();

    while (tile < TILES) {
        int next = tile + GEMM_CTAS;
        if (next < TILES) {
            stage_async(sbase + (cur ^ 1) * (BUF_U32 * 4), x, next, tid);
            CP_COMMIT();
        }

        const uint32_t* As = bufA[cur];
        float acc[4][4][4];
        #pragma unroll
        for (int m = 0; m < 4; m++)
            #pragma unroll
            for (int n = 0; n < 4; n++)
                #pragma unroll
                for (int q = 0; q < 4; q++) acc[m][n][q] = 0.f;

        #pragma unroll 4
        for (int ks = 0; ks < 16; ks++) {
            int k0 = ks * 8;
            uint32_t af[4][4], bf[4][2];
            #pragma unroll
            for (int n = 0; n < 4; n++) {
                int nn = wc * 32 + n * 8 + lr;
                bf[n][0] = Bs[(k0 + lc) * B_STRIDE + nn];
                bf[n][1] = Bs[(k0 + lc + 4) * B_STRIDE + nn];
            }
            #pragma unroll
            for (int m = 0; m < 4; m++) {
                int r = wr * 64 + m * 16 + lr;
                af[m][0] = As[r * A_STRIDE + k0 + lc];
                af[m][1] = As[(r + 8) * A_STRIDE + k0 + lc];
                af[m][2] = As[r * A_STRIDE + k0 + lc + 4];
                af[m][3] = As[(r + 8) * A_STRIDE + k0 + lc + 4];
            }
            #pragma unroll
            for (int m = 0; m < 4; m++)
                #pragma unroll
                for (int n = 0; n < 4; n++)
                    MMA_TF32(acc[m][n][0], acc[m][n][1], acc[m][n][2], acc[m][n][3],
                             af[m][0], af[m][1], af[m][2], af[m][3],
                             bf[n][0], bf[n][1]);
        }

        // epilogue: fp16 (RN). c0,c1 at (row, 2*lc), c2,c3 at (row+8, 2*lc)
        int row0 = tile * M_TILE;
        #pragma unroll
        for (int m = 0; m < 4; m++) {
            int r = row0 + wr * 64 + m * 16 + lr;
            #pragma unroll
            for (int n = 0; n < 4; n++) {
                int col = wc * 32 + n * 8 + lc * 2;
                if (r < N_NODES)
                    *(__half2*)(suph + (size_t)r * 128 + col) =
                        __floats2half2_rn(acc[m][n][0], acc[m][n][1]);
                if (r + 8 < N_NODES)
                    *(__half2*)(suph + (size_t)(r + 8) * 128 + col) =
                        __floats2half2_rn(acc[m][n][2], acc[m][n][3]);
            }
        }

        if (next < TILES) CP_WAIT0();
        __syncthreads();
        cur ^= 1;
        tile = next;
    }
}

// ---------------- 3) gather + bias + residual + relu ------------------------
// One warp per node. Edge metadata loaded cooperatively ONCE (lane j holds
// edge j), then broadcast per-iteration via shfl -> no memory dependency on
// the metadata inside the loop; unroll-4 overlaps 4 support gathers.
// Also resets g_deg/g_ovfn for the next replay (self-cleaning).
__global__ __launch_bounds__(256)
void gather_kernel(const float* __restrict__ y,
                   const float* __restrict__ bias,
                   float* __restrict__ out) {
    int warp = (blockIdx.x * blockDim.x + threadIdx.x) >> 5;
    int lane = threadIdx.x & 31;
    if (warp >= N_NODES) return;
    int node = warp;

    const uint2* sup2 = (const uint2*)g_suph;   // 4 halfs per uint2
    float4 b = ((const float4*)bias)[lane];
    float4 acc = ((const float4*)y)[(size_t)node * 32 + lane];
    acc.x += b.x; acc.y += b.y; acc.z += b.z; acc.w += b.w;

    int dn = g_deg[node];
    int m  = dn < CAP ? dn : CAP;
    int base = node * CAP;

    // cooperative metadata load: lane j holds edge j (and edge 32+j)
    int2 e0 = (lane < m)      ? g_bpack[base + lane]      : make_int2(0, 0);
    int2 e1 = (lane + 32 < m) ? g_bpack[base + 32 + lane] : make_int2(0, 0);

    int m0 = m < 32 ? m : 32;
    #pragma unroll 4
    for (int j = 0; j < m0; j++) {
        int   s = __shfl_sync(0xffffffffu, e0.x, j);
        float v = __int_as_float(__shfl_sync(0xffffffffu, e0.y, j));
        uint2 p = sup2[(size_t)s * 32 + lane];
        float2 f0 = __half22float2(*(__half2*)&p.x);
        float2 f1 = __half22float2(*(__half2*)&p.y);
        acc.x = fmaf(v, f0.x, acc.x);
        acc.y = fmaf(v, f0.y, acc.y);
        acc.z = fmaf(v, f1.x, acc.z);
        acc.w = fmaf(v, f1.y, acc.w);
    }
    #pragma unroll 4
    for (int j = 32; j < m; j++) {
        int   s = __shfl_sync(0xffffffffu, e1.x, j - 32);
        float v = __int_as_float(__shfl_sync(0xffffffffu, e1.y, j - 32));
        uint2 p = sup2[(size_t)s * 32 + lane];
        float2 f0 = __half22float2(*(__half2*)&p.x);
        float2 f1 = __half22float2(*(__half2*)&p.y);
        acc.x = fmaf(v, f0.x, acc.x);
        acc.y = fmaf(v, f0.y, acc.y);
        acc.z = fmaf(v, f1.x, acc.z);
        acc.w = fmaf(v, f1.y, acc.w);
    }

    if (dn > CAP) {  // statistically never; correctness safety net
        int oc = g_ovfn;
        if (oc > OVF_CAP) oc = OVF_CAP;
        for (int k = 0; k < oc; k++) {
            if (g_ovf_dst[k] == node) {
                float v = g_ovf_val[k];
                uint2 p = sup2[(size_t)g_ovf_src[k] * 32 + lane];
                float2 f0 = __half22float2(*(__half2*)&p.x);
                float2 f1 = __half22float2(*(__half2*)&p.y);
                acc.x = fmaf(v, f0.x, acc.x);
                acc.y = fmaf(v, f0.y, acc.y);
                acc.z = fmaf(v, f1.x, acc.z);
                acc.w = fmaf(v, f1.y, acc.w);
            }
        }
    }

    acc.x = fmaxf(acc.x, 0.f);
    acc.y = fmaxf(acc.y, 0.f);
    acc.z = fmaxf(acc.z, 0.f);
    acc.w = fmaxf(acc.w, 0.f);
    ((float4*)out)[(size_t)node * 32 + lane] = acc;

    // self-clean for next replay
    if (lane == 0) g_deg[node] = 0;
    if (node == 0 && lane == 0) g_ovfn = 0;
}

// ---------------- launch -----------------------------------------------------
extern "C" void kernel_launch(void* const* d_in, const int* in_sizes, int n_in,
                              void* d_out, int out_size) {
    const float* x    = (const float*)d_in[0];
    const float* y    = (const float*)d_in[1];
    const int*   esrc = (const int*)d_in[2];
    const int*   edst = (const int*)d_in[3];
    const float* aval = (const float*)d_in[4];
    const float* w    = (const float*)d_in[5];
    const float* bias = (const float*)d_in[6];
    float* out = (float*)d_out;

    __half* suph;
    cudaGetSymbolAddress((void**)&suph, g_suph);

    cudaFuncSetAttribute(gemm_mma_kernel,
                         cudaFuncAttributeMaxDynamicSharedMemorySize, SM_GEMM);

    bucket_kernel<<<(N_EDGES + 255) / 256, 256>>>(esrc, edst, aval);
    gemm_mma_kernel<<<GEMM_CTAS, 256, SM_GEMM>>>(x, w, suph);
    gather_kernel<<<(N_NODES * 32 + 255) / 256, 256>>>(y, bias, out);
}

// round 16
// speedup vs baseline: 1.1521x; 1.0586x over previous
#include <cuda_runtime.h>
#include <cuda_bf16.h>
#include <cuda_fp16.h>
#include <cstdint>

#define N_NODES 100000
#define N_EDGES 1600000
#define D 128
#define CAP 64
#define OVF_CAP 8192

// ---------------- scratch (static device globals; no runtime allocation) ----
__device__ __half g_suph[(size_t)N_NODES * D];         // x @ W in fp16 (25.6 MB)
__device__ int    g_deg[N_NODES];
__device__ int2   g_bpack[(size_t)N_NODES * CAP];      // (src, val bits) packed
__device__ int    g_ovfn;
__device__ int    g_ovf_src[OVF_CAP];
__device__ int    g_ovf_dst[OVF_CAP];
__device__ float  g_ovf_val[OVF_CAP];

__device__ __forceinline__ uint32_t cvt_tf32(float f) {
    uint32_t r;
    asm("cvt.rna.tf32.f32 %0, %1;" : "=r"(r) : "f"(f));
    return r;
}
__device__ __forceinline__ uint32_t smem_u32(const void* p) {
    uint32_t a;
    asm("{ .reg .u64 t; cvta.to.shared.u64 t, %1; cvt.u32.u64 %0, t; }"
        : "=r"(a) : "l"(p));
    return a;
}
#define CP_ASYNC16(saddr, gptr) \
    asm volatile("cp.async.cg.shared.global [%0], [%1], 16;" :: "r"(saddr), "l"(gptr))
#define CP_COMMIT()  asm volatile("cp.async.commit_group;")
#define CP_WAIT0()   asm volatile("cp.async.wait_group 0;")

// mma.sync m16n8k8 tf32: D += A*B (A row-major 16x8, B col-major 8x8)
#define MMA_TF32(d0, d1, d2, d3, a0, a1, a2, a3, b0, b1)                        \
    asm volatile(                                                               \
        "mma.sync.aligned.m16n8k8.row.col.f32.tf32.tf32.f32 "                   \
        "{%0,%1,%2,%3}, {%4,%5,%6,%7}, {%8,%9}, {%0,%1,%2,%3};"                 \
        : "+f"(d0), "+f"(d1), "+f"(d2), "+f"(d3)                                \
        : "r"(a0), "r"(a1), "r"(a2), "r"(a3), "r"(b0), "r"(b1))

// ---------------- 1) zero counters (side stream, warms g_deg in L2) ---------
__global__ void zero_kernel() {
    int i = blockIdx.x * blockDim.x + threadIdx.x;
    if (i < N_NODES) g_deg[i] = 0;
    if (i == 0) g_ovfn = 0;
}

// ---------------- 2) bucket edges by destination (packed 8B stores) ---------
__global__ void bucket_kernel(const int* __restrict__ esrc,
                              const int* __restrict__ edst,
                              const float* __restrict__ aval) {
    int e = blockIdx.x * blockDim.x + threadIdx.x;
    if (e >= N_EDGES) return;
    int d = edst[e];
    int s = esrc[e];
    float v = aval[e];
    int p = atomicAdd(&g_deg[d], 1);
    if (p < CAP) {
        g_bpack[d * CAP + p] = make_int2(s, __float_as_int(v));
    } else {
        int o = atomicAdd(&g_ovfn, 1);
        if (o < OVF_CAP) {
            g_ovf_src[o] = s;
            g_ovf_dst[o] = d;
            g_ovf_val[o] = v;
        }
    }
}

// ---------------- 3) support = x @ W  via mma.sync tf32, fp16 output --------
// Persistent 148 CTAs x 256 threads (8 warps, 2x4). Tile = 128 rows.
// A double-buffered via cp.async, fed RAW fp32 to the tf32 MMA (HW truncates).
// B = W converted to tf32 (RNA) into smem ONCE per CTA; inner loop = LDS+MMA.
// Runs CONCURRENTLY with zero+bucket (separate graph branch): GEMM CTA uses
// only 256 threads + all smem, bucket CTAs (0 smem) co-reside on the SM.
#define A_STRIDE 132
#define B_STRIDE 136
#define M_TILE 128
#define BUF_U32 (M_TILE * A_STRIDE)                   // 16896 u32 = 67584 B
#define B_OFF   (2 * BUF_U32)                         // after both A buffers
#define SM_GEMM (2 * BUF_U32 * 4 + 128 * B_STRIDE * 4)  // 204800 B
#define TILES ((N_NODES + M_TILE - 1) / M_TILE)       // 782
#define GEMM_CTAS 148

__device__ __forceinline__ void stage_async(uint32_t sbuf,
                                            const float* __restrict__ x,
                                            int tile, int tid) {
    int row0 = tile * M_TILE;
    #pragma unroll
    for (int i = 0; i < 16; i++) {
        int idx = tid + i * 256;
        int r = idx >> 5, c4 = idx & 31;
        int gr = row0 + r;
        if (gr >= N_NODES) gr = N_NODES - 1;
        uint32_t sa = sbuf + (uint32_t)(r * A_STRIDE + c4 * 4) * 4u;
        CP_ASYNC16(sa, x + (size_t)gr * 128 + c4 * 4);
    }
}

__global__ __launch_bounds__(256, 1)
void gemm_mma_kernel(const float* __restrict__ x,
                     const float* __restrict__ w,
                     __half* __restrict__ suph) {
    extern __shared__ uint32_t sm[];
    uint32_t* bufA[2] = { sm, sm + BUF_U32 };
    uint32_t* Bs = sm + B_OFF;               // [128][B_STRIDE] tf32
    uint32_t sbase = smem_u32(sm);

    int tid  = threadIdx.x;
    int wid  = tid >> 5;
    int lane = tid & 31;
    int wr   = wid >> 2;        // warp row 0..1 -> rows wr*64
    int wc   = wid & 3;         // warp col 0..3 -> cols wc*32
    int lr   = lane >> 2;       // 0..7
    int lc   = lane & 3;        // 0..3

    int tile = blockIdx.x;
    if (tile >= TILES) return;

    // stage first A tile async, convert B to smem meanwhile
    int cur = 0;
    stage_async(sbase, x, tile, tid);
    CP_COMMIT();
    for (int idx = tid; idx < 128 * 32; idx += 256) {
        int k = idx >> 5, c4 = idx & 31;
        float4 v = ((const float4*)w)[k * 32 + c4];
        uint4 t;
        t.x = cvt_tf32(v.x); t.y = cvt_tf32(v.y);
        t.z = cvt_tf32(v.z); t.w = cvt_tf32(v.w);
        *(uint4*)&Bs[k * B_STRIDE + c4 * 4] = t;
    }
    CP_WAIT0();
    __syncthreads();

    while (tile < TILES) {
        int next = tile + GEMM_CTAS;
        if (next < TILES) {
            stage_async(sbase + (cur ^ 1) * (BUF_U32 * 4), x, next, tid);
            CP_COMMIT();
        }

        const uint32_t* As = bufA[cur];
        float acc[4][4][4];
        #pragma unroll
        for (int m = 0; m < 4; m++)
            #pragma unroll
            for (int n = 0; n < 4; n++)
                #pragma unroll
                for (int q = 0; q < 4; q++) acc[m][n][q] = 0.f;

        #pragma unroll 4
        for (int ks = 0; ks < 16; ks++) {
            int k0 = ks * 8;
            uint32_t af[4][4], bf[4][2];
            #pragma unroll
            for (int n = 0; n < 4; n++) {
                int nn = wc * 32 + n * 8 + lr;
                bf[n][0] = Bs[(k0 + lc) * B_STRIDE + nn];
                bf[n][1] = Bs[(k0 + lc + 4) * B_STRIDE + nn];
            }
            #pragma unroll
            for (int m = 0; m < 4; m++) {
                int r = wr * 64 + m * 16 + lr;
                af[m][0] = As[r * A_STRIDE + k0 + lc];
                af[m][1] = As[(r + 8) * A_STRIDE + k0 + lc];
                af[m][2] = As[r * A_STRIDE + k0 + lc + 4];
                af[m][3] = As[(r + 8) * A_STRIDE + k0 + lc + 4];
            }
            #pragma unroll
            for (int m = 0; m < 4; m++)
                #pragma unroll
                for (int n = 0; n < 4; n++)
                    MMA_TF32(acc[m][n][0], acc[m][n][1], acc[m][n][2], acc[m][n][3],
                             af[m][0], af[m][1], af[m][2], af[m][3],
                             bf[n][0], bf[n][1]);
        }

        // epilogue: fp16 (RN). c0,c1 at (row, 2*lc), c2,c3 at (row+8, 2*lc)
        int row0 = tile * M_TILE;
        #pragma unroll
        for (int m = 0; m < 4; m++) {
            int r = row0 + wr * 64 + m * 16 + lr;
            #pragma unroll
            for (int n = 0; n < 4; n++) {
                int col = wc * 32 + n * 8 + lc * 2;
                if (r < N_NODES)
                    *(__half2*)(suph + (size_t)r * 128 + col) =
                        __floats2half2_rn(acc[m][n][0], acc[m][n][1]);
                if (r + 8 < N_NODES)
                    *(__half2*)(suph + (size_t)(r + 8) * 128 + col) =
                        __floats2half2_rn(acc[m][n][2], acc[m][n][3]);
            }
        }

        if (next < TILES) CP_WAIT0();
        __syncthreads();
        cur ^= 1;
        tile = next;
    }
}

// ---------------- 4) gather + bias + residual + relu (round-10 version) -----
// One warp per destination node. Lane l owns cols 4l..4l+3 (8B fp16 load).
__global__ __launch_bounds__(256)
void gather_kernel(const float* __restrict__ y,
                   const float* __restrict__ bias,
                   float* __restrict__ out) {
    int warp = (blockIdx.x * blockDim.x + threadIdx.x) >> 5;
    int lane = threadIdx.x & 31;
    if (warp >= N_NODES) return;
    int node = warp;

    const uint2* sup2 = (const uint2*)g_suph;   // 4 halfs per uint2
    float4 b = ((const float4*)bias)[lane];
    float4 acc = ((const float4*)y)[(size_t)node * 32 + lane];
    acc.x += b.x; acc.y += b.y; acc.z += b.z; acc.w += b.w;

    int dn = g_deg[node];
    int m  = dn < CAP ? dn : CAP;
    int base = node * CAP;

    #pragma unroll 2
    for (int j = 0; j < m; j++) {
        int2 e = g_bpack[base + j];
        float v = __int_as_float(e.y);
        uint2 p = sup2[(size_t)e.x * 32 + lane];
        float2 f0 = __half22float2(*(__half2*)&p.x);
        float2 f1 = __half22float2(*(__half2*)&p.y);
        acc.x = fmaf(v, f0.x, acc.x);
        acc.y = fmaf(v, f0.y, acc.y);
        acc.z = fmaf(v, f1.x, acc.z);
        acc.w = fmaf(v, f1.y, acc.w);
    }

    if (dn > CAP) {  // statistically never; correctness safety net
        int oc = g_ovfn;
        if (oc > OVF_CAP) oc = OVF_CAP;
        for (int k = 0; k < oc; k++) {
            if (g_ovf_dst[k] == node) {
                int s   = g_ovf_src[k];
                float v = g_ovf_val[k];
                uint2 p = sup2[(size_t)s * 32 + lane];
                float2 f0 = __half22float2(*(__half2*)&p.x);
                float2 f1 = __half22float2(*(__half2*)&p.y);
                acc.x = fmaf(v, f0.x, acc.x);
                acc.y = fmaf(v, f0.y, acc.y);
                acc.z = fmaf(v, f1.x, acc.z);
                acc.w = fmaf(v, f1.y, acc.w);
            }
        }
    }

    acc.x = fmaxf(acc.x, 0.f);
    acc.y = fmaxf(acc.y, 0.f);
    acc.z = fmaxf(acc.z, 0.f);
    acc.w = fmaxf(acc.w, 0.f);
    ((float4*)out)[(size_t)node * 32 + lane] = acc;
}

// ---------------- launch: fork-join graph ------------------------------------
// default stream:  [record evF] ---- gemm ---------------- [wait evJ] gather
// side stream:     [wait evF] zero -> bucket [record evJ]
// Streams/events are created on the FIRST call (the correctness run, which
// precedes graph capture), so the capture call performs only launches and
// event record/wait ops — the standard stream-capture fork-join pattern.
extern "C" void kernel_launch(void* const* d_in, const int* in_sizes, int n_in,
                              void* d_out, int out_size) {
    const float* x    = (const float*)d_in[0];
    const float* y    = (const float*)d_in[1];
    const int*   esrc = (const int*)d_in[2];
    const int*   edst = (const int*)d_in[3];
    const float* aval = (const float*)d_in[4];
    const float* w    = (const float*)d_in[5];
    const float* bias = (const float*)d_in[6];
    float* out = (float*)d_out;

    __half* suph;
    cudaGetSymbolAddress((void**)&suph, g_suph);

    static cudaStream_t s2 = [] {
        cudaStream_t s;
        cudaStreamCreateWithFlags(&s, cudaStreamNonBlocking);
        return s;
    }();
    static cudaEvent_t evF = [] {
        cudaEvent_t e;
        cudaEventCreateWithFlags(&e, cudaEventDisableTiming);
        return e;
    }();
    static cudaEvent_t evJ = [] {
        cudaEvent_t e;
        cudaEventCreateWithFlags(&e, cudaEventDisableTiming);
        return e;
    }();
    static bool attr_set = [] {
        cudaFuncSetAttribute(gemm_mma_kernel,
                             cudaFuncAttributeMaxDynamicSharedMemorySize, SM_GEMM);
        return true;
    }();
    (void)attr_set;

    // fork
    cudaEventRecord(evF, 0);
    cudaStreamWaitEvent(s2, evF, 0);

    // side branch: zero -> bucket
    zero_kernel<<<(N_NODES + 255) / 256, 256, 0, s2>>>();
    bucket_kernel<<<(N_EDGES + 255) / 256, 256, 0, s2>>>(esrc, edst, aval);
    cudaEventRecord(evJ, s2);

    // main branch: gemm (overlaps with side branch)
    gemm_mma_kernel<<<GEMM_CTAS, 256, SM_GEMM>>>(x, w, suph);

    // join, then gather
    cudaStreamWaitEvent(0, evJ, 0);
    gather_kernel<<<(N_NODES * 32 + 255) / 256, 256>>>(y, bias, out);
}